// round 10
// baseline (speedup 1.0000x reference)
#include <cuda_runtime.h>

#define D1C   16
#define D2C   16
#define NCC   64
#define NCPCC 8
// Inner o-block: 128 data floats + 8 norms + 4 pad = 140 floats.
// Quad stride 35 == 3 (mod 8) -> bo rows spread across all 8 quad-banks.
#define ISTRIDE 140

typedef unsigned long long u64;

__device__ __forceinline__ u64 ffma2(u64 a, u64 b, u64 c) {
    u64 d; asm("fma.rn.f32x2 %0, %1, %2, %3;" : "=l"(d) : "l"(a), "l"(b), "l"(c)); return d;
}
__device__ __forceinline__ u64 fmul2(u64 a, u64 b) {
    u64 d; asm("mul.rn.f32x2 %0, %1, %2;" : "=l"(d) : "l"(a), "l"(b)); return d;
}
__device__ __forceinline__ float hsum2(u64 v) {
    float lo, hi;
    asm("mov.b64 {%0, %1}, %2;" : "=f"(lo), "=f"(hi) : "l"(v));
    return lo + hi;
}
__device__ __forceinline__ u64 packf2(float lo, float hi) {
    u64 r; asm("mov.b64 %0, {%1, %2};" : "=l"(r) : "f"(lo), "f"(hi)); return r;
}
// Data-dependent zero: LOP3 with immLut 0x00. Opaque to ptxas -> any address
// formed with it cannot be hoisted above the computation of `v`.
__device__ __forceinline__ int dep_zero(int v) {
    int z; asm("lop3.b32 %0, %1, %1, %1, 0x00;" : "=r"(z) : "r"(v)); return z;
}

__global__ void __launch_bounds__(256, 4)
cluster_kernel(const float* __restrict__ x,
               const float* __restrict__ co,
               const float* __restrict__ ci,
               float* __restrict__ out, int n)
{
    __shared__ __align__(16) float s_oc[NCC * D1C];     // outer centers [c][d]
    __shared__ __align__(16) float s_on[NCC];           // outer ||c||^2
    __shared__ __align__(16) float s_in[NCC * ISTRIDE]; // inner [o]{128 data | 8 norms | pad}

    const int tid = threadIdx.x;

    for (int idx = tid; idx < NCC * D1C; idx += 256)
        s_oc[idx] = co[idx];
    for (int idx = tid; idx < NCC * NCPCC * D2C; idx += 256) {
        int o = idx >> 7, r = idx & 127;            // ci is [o][k][d]
        s_in[o * ISTRIDE + r] = ci[idx];
    }
    __syncthreads();

    for (int c = tid; c < NCC; c += 256) {
        float s = 0.f;
        #pragma unroll
        for (int d = 0; d < D1C; d++) { float v = s_oc[c * D1C + d]; s += v * v; }
        s_on[c] = s;
    }
    for (int idx = tid; idx < NCC * NCPCC; idx += 256) {
        int o = idx >> 3, k = idx & 7;
        float s = 0.f;
        #pragma unroll
        for (int d = 0; d < D2C; d++) { float v = s_in[o * ISTRIDE + k * D2C + d]; s += v * v; }
        s_in[o * ISTRIDE + 128 + k] = s;            // norms in pad region
    }
    __syncthreads();

    const int GS   = gridDim.x * blockDim.x;
    const u64 neg2 = packf2(-2.f, -2.f);

    // Each thread: 2 CONTIGUOUS points. n is even in this problem, so pairs
    // are always full (defensive guard kept for the ragged case).
    for (int p0 = (blockIdx.x * blockDim.x + tid) * 2; p0 < n; p0 += 2 * GS) {
        const int  i1   = (p0 + 1 < n) ? p0 + 1 : p0;
        const bool pair = (p0 + 1 < n);

        // ---- x1 (dims 0-15) of both points, pre-scaled by -2, packed f32x2 ----
        const ulonglong2* xa = (const ulonglong2*)(x + (size_t)p0 * 32);
        const ulonglong2* xb = (const ulonglong2*)(x + (size_t)i1 * 32);
        u64 px0[8], px1[8];
        {
            ulonglong2 w0 = xa[0], w1 = xa[1], w2 = xa[2], w3 = xa[3];
            px0[0] = fmul2(w0.x, neg2); px0[1] = fmul2(w0.y, neg2);
            px0[2] = fmul2(w1.x, neg2); px0[3] = fmul2(w1.y, neg2);
            px0[4] = fmul2(w2.x, neg2); px0[5] = fmul2(w2.y, neg2);
            px0[6] = fmul2(w3.x, neg2); px0[7] = fmul2(w3.y, neg2);
        }
        {
            ulonglong2 w0 = xb[0], w1 = xb[1], w2 = xb[2], w3 = xb[3];
            px1[0] = fmul2(w0.x, neg2); px1[1] = fmul2(w0.y, neg2);
            px1[2] = fmul2(w1.x, neg2); px1[3] = fmul2(w1.y, neg2);
            px1[4] = fmul2(w2.x, neg2); px1[5] = fmul2(w2.y, neg2);
            px1[6] = fmul2(w3.x, neg2); px1[7] = fmul2(w3.y, neg2);
        }

        // ---- outer argmin: d = ||c||^2 + sum((-2x).c), strict <, first wins ----
        float best0 = 3.402823466e38f, best1 = 3.402823466e38f;
        int   bo0 = 0, bo1 = 0;

        #pragma unroll 1
        for (int cg = 0; cg < NCC / 4; cg++) {
            float4 nr = *(const float4*)(s_on + cg * 4);
            float nrr[4] = {nr.x, nr.y, nr.z, nr.w};
            #pragma unroll
            for (int j = 0; j < 4; j++) {
                int c = cg * 4 + j;
                const ulonglong2* cp = (const ulonglong2*)(s_oc + c * D1C);
                ulonglong2 m0 = cp[0], m1 = cp[1], m2 = cp[2], m3 = cp[3];
                u64 ninit = packf2(nrr[j], 0.f);

                u64 a0 = ffma2(px0[0], m0.x, ninit);
                u64 a1 = ffma2(px1[0], m0.x, ninit);
                a0 = ffma2(px0[1], m0.y, a0);  a1 = ffma2(px1[1], m0.y, a1);
                a0 = ffma2(px0[2], m1.x, a0);  a1 = ffma2(px1[2], m1.x, a1);
                a0 = ffma2(px0[3], m1.y, a0);  a1 = ffma2(px1[3], m1.y, a1);
                a0 = ffma2(px0[4], m2.x, a0);  a1 = ffma2(px1[4], m2.x, a1);
                a0 = ffma2(px0[5], m2.y, a0);  a1 = ffma2(px1[5], m2.y, a1);
                a0 = ffma2(px0[6], m3.x, a0);  a1 = ffma2(px1[6], m3.x, a1);
                a0 = ffma2(px0[7], m3.y, a0);  a1 = ffma2(px1[7], m3.y, a1);

                float dd0 = hsum2(a0), dd1 = hsum2(a1);
                if (dd0 < best0) { best0 = dd0; bo0 = c; }
                if (dd1 < best1) { best1 = dd1; bo1 = c; }
            }
        }

        // ---- inner argmin. x2 reloaded (L1/L2-hot) with an address that
        //      data-depends on bo so ptxas CANNOT hoist it above the outer
        //      loop (register-pressure control). ----
        float res0, res1;
        {
            const ulonglong2* q = (const ulonglong2*)(x + (size_t)p0 * 32 + dep_zero(bo0)) + 4;
            ulonglong2 v0 = q[0], v1 = q[1], v2 = q[2], v3 = q[3];
            u64 py[8] = {fmul2(v0.x, neg2), fmul2(v0.y, neg2),
                         fmul2(v1.x, neg2), fmul2(v1.y, neg2),
                         fmul2(v2.x, neg2), fmul2(v2.y, neg2),
                         fmul2(v3.x, neg2), fmul2(v3.y, neg2)};

            const float* ib = s_in + bo0 * ISTRIDE;
            float4 nA = *(const float4*)(ib + 128);
            float4 nB = *(const float4*)(ib + 132);
            float nk[8] = {nA.x, nA.y, nA.z, nA.w, nB.x, nB.y, nB.z, nB.w};

            float bd = 3.402823466e38f; int bk = 0;
            #pragma unroll
            for (int k = 0; k < NCPCC; k++) {
                const ulonglong2* kp = (const ulonglong2*)(ib + k * D2C);
                ulonglong2 ma = kp[0], mb = kp[1], mc = kp[2], md = kp[3];
                u64 s = ffma2(py[0], ma.x, packf2(nk[k], 0.f));
                s = ffma2(py[1], ma.y, s);
                s = ffma2(py[2], mb.x, s);
                s = ffma2(py[3], mb.y, s);
                s = ffma2(py[4], mc.x, s);
                s = ffma2(py[5], mc.y, s);
                s = ffma2(py[6], md.x, s);
                s = ffma2(py[7], md.y, s);
                float dd = hsum2(s);
                if (dd < bd) { bd = dd; bk = k; }
            }
            res0 = (float)(bo0 * NCPCC + bk);
        }
        {
            const ulonglong2* q = (const ulonglong2*)(x + (size_t)i1 * 32 + dep_zero(bo1)) + 4;
            ulonglong2 v0 = q[0], v1 = q[1], v2 = q[2], v3 = q[3];
            u64 py[8] = {fmul2(v0.x, neg2), fmul2(v0.y, neg2),
                         fmul2(v1.x, neg2), fmul2(v1.y, neg2),
                         fmul2(v2.x, neg2), fmul2(v2.y, neg2),
                         fmul2(v3.x, neg2), fmul2(v3.y, neg2)};

            const float* ib = s_in + bo1 * ISTRIDE;
            float4 nA = *(const float4*)(ib + 128);
            float4 nB = *(const float4*)(ib + 132);
            float nk[8] = {nA.x, nA.y, nA.z, nA.w, nB.x, nB.y, nB.z, nB.w};

            float bd = 3.402823466e38f; int bk = 0;
            #pragma unroll
            for (int k = 0; k < NCPCC; k++) {
                const ulonglong2* kp = (const ulonglong2*)(ib + k * D2C);
                ulonglong2 ma = kp[0], mb = kp[1], mc = kp[2], md = kp[3];
                u64 s = ffma2(py[0], ma.x, packf2(nk[k], 0.f));
                s = ffma2(py[1], ma.y, s);
                s = ffma2(py[2], mb.x, s);
                s = ffma2(py[3], mb.y, s);
                s = ffma2(py[4], mc.x, s);
                s = ffma2(py[5], mc.y, s);
                s = ffma2(py[6], md.x, s);
                s = ffma2(py[7], md.y, s);
                float dd = hsum2(s);
                if (dd < bd) { bd = dd; bk = k; }
            }
            res1 = (float)(bo1 * NCPCC + bk);
        }

        if (pair) {
            *(float2*)(out + p0) = make_float2(res0, res1);  // p0 even -> 8B aligned
        } else {
            out[p0] = res0;
        }
    }
}

extern "C" void kernel_launch(void* const* d_in, const int* in_sizes, int n_in,
                              void* d_out, int out_size)
{
    // Bind inputs by unique element counts (robust to metadata ordering).
    const float* x  = 0; const float* co = 0; const float* ci = 0;
    long long x_elems = 0;
    for (int i = 0; i < n_in; i++) {
        int sz = in_sizes[i];
        if (sz == NCC * D1C)              co = (const float*)d_in[i];
        else if (sz == NCC * NCPCC * D2C) ci = (const float*)d_in[i];
        else { x = (const float*)d_in[i]; x_elems = sz; }
    }
    if (!x)  { x  = (const float*)d_in[0]; x_elems = in_sizes[0]; }
    if (!co)   co = (const float*)d_in[1];
    if (!ci)   ci = (const float*)d_in[2];

    float* out = (float*)d_out;
    int n = (int)(x_elems / (D1C + D2C));
    if (n <= 0 || n > out_size) n = out_size;

    int blocks = 592;  // 148 SMs x 4 resident CTAs, one wave, P=2 contiguous
    cluster_kernel<<<blocks, 256>>>(x, co, ci, out, n);
}